// round 14
// baseline (speedup 1.0000x reference)
#include <cuda_runtime.h>

#define NB   32        // batch
#define NE   200000    // entities
#define NT   1000000   // triples
#define NR   256       // relations
#define DQ   768       // question dim
#define DIN  1280      // DQ + 2*NR
#define NEB  (NE * NB) // 6.4M floats
#define NJ   257       // 256 W_inf rows + 1 W_att row

// ---- device scratch (static; zero at load; k_combine restores the all-zero
// state of g_xh / g_lm[NE..) / g_rT each call, so replays are identical) ----
__device__ __align__(16) float g_x0T[NEB];     // transposed seed x (active rows)
__device__ __align__(16) float g_xh[3 * NEB];  // hop outputs (self-cleaned)
__device__ __align__(16) float g_rT[3 * NR * NB]; // r per hop (self-cleaned)
__device__ float g_c[3 * NB];                  // attention logits per hop
__device__ unsigned g_lm[4 * NE];              // lane-activity mask per hop

// ======= kernel 0: zero g_c (must precede phase1's atomics; tiny) ===========
__global__ void k_zero_c() {
    int i = threadIdx.x;
    if (i < 3 * NB) g_c[i] = 0.f;
}

// ================= phase 1: transpose + hop-0 lane mask + gemm_base =========
#define B_GB (NJ * 4)                          // 1028
#define B_TX (NE / 32)                         // 6250
#define B_P1 (B_GB + B_TX)

__global__ void k_phase1(const float* __restrict__ x,
                         const float* __restrict__ h_q,
                         const float* __restrict__ W_inf,
                         const float* __restrict__ W_att) {
    int bid = blockIdx.x;
    int tid = threadIdx.x;
    int lane = tid & 31, ty = tid >> 5;

    if (bid < B_GB) {
        // ---- gemm_base: r_0/c_0 = h_q @ [W_inf; W_att][:, :768].T ----
        __shared__ float sh[192][33];
        __shared__ float sr[8][32];
        int j = bid >> 2;
        int d0 = (bid & 3) * 192;
#pragma unroll
        for (int k = 0; k < 24; k++) {                  // 6144 elems, coalesced
            int idx = tid + k * 256;
            int b = idx / 192, d = idx % 192;
            sh[d][b] = h_q[(size_t)b * DQ + d0 + d];
        }
        __syncthreads();
        const float* w = (j == 256) ? W_att : W_inf + (size_t)j * DIN;
        int dd = ty * 24;
        float a0 = 0.f, a1 = 0.f, a2 = 0.f, a3 = 0.f;
#pragma unroll
        for (int d = dd; d < dd + 24; d += 4) {
            a0 += sh[d + 0][lane] * w[d0 + d + 0];
            a1 += sh[d + 1][lane] * w[d0 + d + 1];
            a2 += sh[d + 2][lane] * w[d0 + d + 2];
            a3 += sh[d + 3][lane] * w[d0 + d + 3];
        }
        sr[ty][lane] = (a0 + a1) + (a2 + a3);
        __syncthreads();
        if (ty == 0) {
            float t = 0.f;
#pragma unroll
            for (int k = 0; k < 8; k++) t += sr[k][lane];
            if (j == 256) atomicAdd(&g_c[lane], t);
            else          atomicAdd(&g_rT[j * NB + lane], t);
        }
    } else {
        // ---- transpose x (B x NE) -> (NE x B), sparse writes + hop-0 lane mask
        __shared__ float s[32][33];
        int cbase = (bid - B_GB) * 32;
#pragma unroll
        for (int row = ty; row < 32; row += 8)          // row = b
            s[row][lane] = x[(size_t)row * NE + cbase + lane];
        __syncthreads();
#pragma unroll
        for (int row = ty; row < 32; row += 8) {        // row = entity offset
            float v = s[lane][row];                     // lane = b
            unsigned b = __ballot_sync(0xffffffffu, v != 0.0f);
            if (b) g_x0T[(size_t)(cbase + row) * NB + lane] = v;
            if (lane == 0) g_lm[cbase + row] = b;       // exact hop-0 lane mask
        }
    }
}

// ================= shared device pieces for phases 2-4 ======================
// hop gemm increment: out_hop = hop0_out + r_parts @ W[:, 768:768+hop*256].T
__device__ __forceinline__ void gemm_hop_body(const float* __restrict__ W_inf,
                                              const float* __restrict__ W_att,
                                              int hop, int j, int yb,
                                              int lane, int ty) {
    __shared__ float s[8][32];
    const float* w = (j == 256) ? W_att : W_inf + (size_t)j * DIN;
    int kk0 = yb * 128 + ty * 16;
    int seg = kk0 >> 8;
    int within = kk0 & 255;
    const float* rsrc = g_rT + (hop - 1 - seg) * NR * NB;
    const float* wd = w + DQ + kk0;
    float a0 = 0.f, a1 = 0.f;
#pragma unroll
    for (int k = 0; k < 16; k += 2) {
        a0 += rsrc[(within + k) * NB + lane] * wd[k];
        a1 += rsrc[(within + k + 1) * NB + lane] * wd[k + 1];
    }
    s[ty][lane] = a0 + a1;
    __syncthreads();
    if (ty == 0) {
        float t = 0.f;
#pragma unroll
        for (int k = 0; k < 8; k++) t += s[k][lane];
        if (yb == 0)
            t += (j == 256) ? g_c[lane] : g_rT[j * NB + lane];
        if (j == 256) atomicAdd(&g_c[hop * NB + lane], t);
        else          atomicAdd(&g_rT[hop * NR * NB + j * NB + lane], t);
    }
}

// scatter: lane-mask-gated gather*relation -> red.v4 scatter; produces lm[hop+1]
__device__ __forceinline__ void scatter_body(const int* __restrict__ subj,
                                             const int* __restrict__ rel,
                                             const int* __restrict__ obj,
                                             int hop, int sblk, int tid) {
    const float* __restrict__ rT = g_rT + hop * NR * NB;
    const float* __restrict__ xin = (hop == 0) ? g_x0T : (g_xh + (hop - 1) * NEB);
    float* xout = g_xh + hop * NEB;
    const unsigned* __restrict__ lmin = g_lm + hop * NE;
    unsigned* lmout = g_lm + (hop + 1) * NE;

    int lane = tid & 31;
    int sub = lane >> 3, quad = lane & 7;
    int t = sblk * 256 + tid;

    int s_i = 0, r_i = 0, o_i = 0;
    unsigned lm_i = 0;
    if (t < NT) {
        s_i = subj[t];
        lm_i = lmin[s_i];
        if (lm_i) { r_i = rel[t]; o_i = obj[t]; }
    }
    unsigned bal = __ballot_sync(0xffffffffu, lm_i != 0);
    while (bal) {
        unsigned b = bal;
        int i0 = __ffs(b) - 1; b &= b - 1;
        int i1 = __ffs(b) - 1; b &= b - 1;
        int i2 = __ffs(b) - 1; b &= b - 1;
        int i3 = __ffs(b) - 1; b &= b - 1;
        bal = b;
        int myi = (sub == 0) ? i0 : (sub == 1) ? i1 : (sub == 2) ? i2 : i3;
        bool on = (myi >= 0);
        int src = on ? myi : 0;
        int s = __shfl_sync(0xffffffffu, s_i, src);
        int r = __shfl_sync(0xffffffffu, r_i, src);
        int o = __shfl_sync(0xffffffffu, o_i, src);
        unsigned lmw = __shfl_sync(0xffffffffu, lm_i, src);
        unsigned nib = (lmw >> (quad * 4)) & 0xFu;
        unsigned m4 = 0;
        if (on && nib) {
            float4 xv = *reinterpret_cast<const float4*>(&xin[(size_t)s * NB + quad * 4]);
            float4 rv = *reinterpret_cast<const float4*>(&rT[r * NB + quad * 4]);
            float4 p;
            p.x = xv.x * rv.x; p.y = xv.y * rv.y;
            p.z = xv.z * rv.z; p.w = xv.w * rv.w;
            m4 = (p.x != 0.f) | ((p.y != 0.f) << 1) |
                 ((p.z != 0.f) << 2) | ((p.w != 0.f) << 3);
            if (m4) {
                float* dst = &xout[(size_t)o * NB + quad * 4];
                asm volatile("red.global.add.v4.f32 [%0], {%1,%2,%3,%4};"
                             :: "l"(dst), "f"(p.x), "f"(p.y), "f"(p.z), "f"(p.w)
                             : "memory");
            }
        }
        unsigned mm = m4 << (quad * 4);
        mm |= __shfl_down_sync(0xffffffffu, mm, 4, 8);
        mm |= __shfl_down_sync(0xffffffffu, mm, 2, 8);
        mm |= __shfl_down_sync(0xffffffffu, mm, 1, 8);
        if (on && quad == 0 && mm)
            atomicOr(&lmout[o], mm);
    }
}

#define B_SC ((NT + 255) / 256)   // 3907 scatter blocks

// ============ phase 2: gemm_hop1 (NJ*2 blocks) + scatter hop0 ===============
__global__ void k_phase2(const int* __restrict__ subj, const int* __restrict__ rel,
                         const int* __restrict__ obj,
                         const float* __restrict__ W_inf,
                         const float* __restrict__ W_att) {
    int bid = blockIdx.x, tid = threadIdx.x;
    if (bid < NJ * 2)
        gemm_hop_body(W_inf, W_att, 1, bid >> 1, bid & 1, tid & 31, tid >> 5);
    else
        scatter_body(subj, rel, obj, 0, bid - NJ * 2, tid);
}

// ============ phase 3: gemm_hop2 (NJ*4 blocks) + scatter hop1 ===============
__global__ void k_phase3(const int* __restrict__ subj, const int* __restrict__ rel,
                         const int* __restrict__ obj,
                         const float* __restrict__ W_inf,
                         const float* __restrict__ W_att) {
    int bid = blockIdx.x, tid = threadIdx.x;
    if (bid < NJ * 4)
        gemm_hop_body(W_inf, W_att, 2, bid >> 2, bid & 3, tid & 31, tid >> 5);
    else
        scatter_body(subj, rel, obj, 1, bid - NJ * 4, tid);
}

// ============ phase 4: scatter hop2 =========================================
__global__ void k_phase4(const int* __restrict__ subj, const int* __restrict__ rel,
                         const int* __restrict__ obj) {
    scatter_body(subj, rel, obj, 2, blockIdx.x, threadIdx.x);
}

// ==== phase 5: softmax + masked combine + transpose out + state restore =====
// Blocks [0, NE/32): combine 32 entity rows, zero the xh rows they read,
// reset lm[1..3]. Blocks [NE/32, +24): zero g_rT (not read by combine).
__global__ void k_combine(float* __restrict__ out) {
    int bx = blockIdx.x;
    if (bx >= NE / 32) {
        int i = (bx - NE / 32) * 256 + threadIdx.x;     // 24*256 = 6144 float4
        if (i < 3 * NR * NB / 4)
            reinterpret_cast<float4*>(g_rT)[i] = make_float4(0.f, 0.f, 0.f, 0.f);
        return;
    }
    __shared__ float s[32][33];
    int lane = threadIdx.x & 31, ty = threadIdx.x >> 5;
    float c0 = g_c[lane], c1 = g_c[NB + lane], c2 = g_c[2 * NB + lane];
    float m = fmaxf(c0, fmaxf(c1, c2));
    float e0 = expf(c0 - m), e1 = expf(c1 - m), e2 = expf(c2 - m);
    float inv = 1.0f / (e0 + e1 + e2);
    float a0 = e0 * inv, a1 = e1 * inv, a2 = e2 * inv;

    int ebase = bx * 32;
#pragma unroll
    for (int row = ty; row < 32; row += 8) {           // row = e offset, lane = b
        int e = ebase + row;
        int idx = e * NB + lane;
        unsigned m1 = g_lm[NE + e], m2 = g_lm[2 * NE + e], m3 = g_lm[3 * NE + e];
        float v = 0.f;
        if (m1) { v += a0 * g_xh[idx];           g_xh[idx] = 0.f; }
        if (m2) { v += a1 * g_xh[NEB + idx];     g_xh[NEB + idx] = 0.f; }
        if (m3) { v += a2 * g_xh[2 * NEB + idx]; g_xh[2 * NEB + idx] = 0.f; }
        if (lane == 0) {                                // reset lm after reads
            if (m1) g_lm[NE + e] = 0u;
            if (m2) g_lm[2 * NE + e] = 0u;
            if (m3) g_lm[3 * NE + e] = 0u;
        }
        s[row][lane] = v;
    }
    __syncthreads();
#pragma unroll
    for (int row = ty; row < 32; row += 8)             // row = b, lane = e offset
        out[(size_t)row * NE + ebase + lane] = s[lane][row];
}

extern "C" void kernel_launch(void* const* d_in, const int* in_sizes, int n_in,
                              void* d_out, int out_size) {
    const float* x     = (const float*)d_in[0];
    const float* h_q   = (const float*)d_in[1];
    const float* W_inf = (const float*)d_in[2];
    const float* W_att = (const float*)d_in[3];
    const int*   subj  = (const int*)d_in[4];
    const int*   rel   = (const int*)d_in[5];
    const int*   obj   = (const int*)d_in[6];
    float* out = (float*)d_out;

    k_zero_c<<<1, 128>>>();
    k_phase1<<<B_P1, 256>>>(x, h_q, W_inf, W_att);
    k_phase2<<<NJ * 2 + B_SC, 256>>>(subj, rel, obj, W_inf, W_att);
    k_phase3<<<NJ * 4 + B_SC, 256>>>(subj, rel, obj, W_inf, W_att);
    k_phase4<<<B_SC, 256>>>(subj, rel, obj);
    k_combine<<<NE / 32 + 24, 256>>>(out);
}

// round 15
// speedup vs baseline: 2.6484x; 2.6484x over previous
#include <cuda_runtime.h>

#define NB   32        // batch
#define NE   200000    // entities
#define NT   1000000   // triples
#define NR   256       // relations
#define DQ   768       // question dim
#define DIN  1280      // DQ + 2*NR
#define NEB  (NE * NB) // 6.4M floats
#define NJ   257       // 256 W_inf rows + 1 W_att row

// ---- device scratch (static; no allocation) ----
__device__ float g_x0T[NEB];           // transposed seed x: [e][b] (active rows)
__device__ float g_xh[3 * NEB];        // hop outputs, entity-major
__device__ float g_rT[3 * NR * NB];    // r per hop: [j][b]
__device__ float g_c[3 * NB];          // attention logits per hop
__device__ unsigned g_lm[4 * NE];      // per-entity 32-bit lane-activity mask per hop

// ======= kernel 0: zero gemm accumulators (must precede phase1's atomics) ===
__global__ void k_zero_acc() {
    int i = blockIdx.x * blockDim.x + threadIdx.x;
    if (i < 3 * NR * NB) g_rT[i] = 0.f;
    if (i < 3 * NB) g_c[i] = 0.f;
}

// ================= phase 1: transpose + big zeroing + gemm_base =============
#define B_GB (NJ * 4)                          // 1028
#define B_TX (NE / 32)                         // 6250
#define B_ZX ((3 * NEB / 4 + 1023) / 1024)     // 4688
#define B_ZM ((3 * NE + 255) / 256)            // 2344
#define B_P1 (B_GB + B_TX + B_ZX + B_ZM)

__global__ void k_phase1(const float* __restrict__ x,
                         const float* __restrict__ h_q,
                         const float* __restrict__ W_inf,
                         const float* __restrict__ W_att) {
    int bid = blockIdx.x;
    int tid = threadIdx.x;
    int lane = tid & 31, ty = tid >> 5;

    if (bid < B_GB) {
        // ---- gemm_base: r_0/c_0 = h_q @ [W_inf; W_att][:, :768].T ----
        __shared__ float sh[192][33];
        __shared__ float sr[8][32];
        int j = bid >> 2;
        int d0 = (bid & 3) * 192;
#pragma unroll
        for (int k = 0; k < 24; k++) {                  // 6144 elems, coalesced
            int idx = tid + k * 256;
            int b = idx / 192, d = idx % 192;
            sh[d][b] = h_q[(size_t)b * DQ + d0 + d];
        }
        __syncthreads();
        const float* w = (j == 256) ? W_att : W_inf + (size_t)j * DIN;
        int dd = ty * 24;
        float a0 = 0.f, a1 = 0.f, a2 = 0.f, a3 = 0.f;
#pragma unroll
        for (int d = dd; d < dd + 24; d += 4) {
            a0 += sh[d + 0][lane] * w[d0 + d + 0];
            a1 += sh[d + 1][lane] * w[d0 + d + 1];
            a2 += sh[d + 2][lane] * w[d0 + d + 2];
            a3 += sh[d + 3][lane] * w[d0 + d + 3];
        }
        sr[ty][lane] = (a0 + a1) + (a2 + a3);
        __syncthreads();
        if (ty == 0) {
            float t = 0.f;
#pragma unroll
            for (int k = 0; k < 8; k++) t += sr[k][lane];
            if (j == 256) atomicAdd(&g_c[lane], t);
            else          atomicAdd(&g_rT[j * NB + lane], t);
        }
    } else if (bid < B_GB + B_TX) {
        // ---- transpose x (B x NE) -> (NE x B), sparse writes + hop-0 lane mask
        __shared__ float s[32][33];
        int cbase = (bid - B_GB) * 32;
#pragma unroll
        for (int row = ty; row < 32; row += 8)          // row = b
            s[row][lane] = x[(size_t)row * NE + cbase + lane];
        __syncthreads();
#pragma unroll
        for (int row = ty; row < 32; row += 8) {        // row = entity offset
            float v = s[lane][row];                     // lane = b
            unsigned b = __ballot_sync(0xffffffffu, v != 0.0f);
            if (b) g_x0T[(size_t)(cbase + row) * NB + lane] = v;
            if (lane == 0) g_lm[cbase + row] = b;       // exact hop-0 lane mask
        }
    } else if (bid < B_GB + B_TX + B_ZX) {
        // ---- zero g_xh (4 float4 per thread): L2-prefetches scatter dests ----
        int base = (bid - B_GB - B_TX) * 1024 + tid;
        const int nq = 3 * NEB / 4;
#pragma unroll
        for (int k = 0; k < 4; k++) {
            int i = base + k * 256;
            if (i < nq)
                reinterpret_cast<float4*>(g_xh)[i] = make_float4(0.f, 0.f, 0.f, 0.f);
        }
    } else {
        // ---- zero lm[1..3] ----
        int i = (bid - B_GB - B_TX - B_ZX) * 256 + tid;
        if (i < 3 * NE) g_lm[NE + i] = 0u;
    }
}

// ================= shared device pieces for phases 2-4 ======================
// hop gemm increment: out_hop = hop0_out + r_parts @ W[:, 768:768+hop*256].T
__device__ __forceinline__ void gemm_hop_body(const float* __restrict__ W_inf,
                                              const float* __restrict__ W_att,
                                              int hop, int j, int yb,
                                              int lane, int ty) {
    __shared__ float s[8][32];
    const float* w = (j == 256) ? W_att : W_inf + (size_t)j * DIN;
    int kk0 = yb * 128 + ty * 16;
    int seg = kk0 >> 8;
    int within = kk0 & 255;
    const float* rsrc = g_rT + (hop - 1 - seg) * NR * NB;
    const float* wd = w + DQ + kk0;
    float a0 = 0.f, a1 = 0.f;
#pragma unroll
    for (int k = 0; k < 16; k += 2) {
        a0 += rsrc[(within + k) * NB + lane] * wd[k];
        a1 += rsrc[(within + k + 1) * NB + lane] * wd[k + 1];
    }
    s[ty][lane] = a0 + a1;
    __syncthreads();
    if (ty == 0) {
        float t = 0.f;
#pragma unroll
        for (int k = 0; k < 8; k++) t += s[k][lane];
        if (yb == 0)
            t += (j == 256) ? g_c[lane] : g_rT[j * NB + lane];
        if (j == 256) atomicAdd(&g_c[hop * NB + lane], t);
        else          atomicAdd(&g_rT[hop * NR * NB + j * NB + lane], t);
    }
}

// scatter: lane-mask-gated gather*relation -> red.v4 scatter; produces lm[hop+1].
// 8 active triples per warp-iteration (4 lanes/triple, 2 gated float4s/lane),
// selected with __fns to avoid a serial ffs chain -> 2x memory-level parallelism.
__device__ __forceinline__ void scatter_body(const int* __restrict__ subj,
                                             const int* __restrict__ rel,
                                             const int* __restrict__ obj,
                                             int hop, int sblk, int tid) {
    const float* __restrict__ rT = g_rT + hop * NR * NB;
    const float* __restrict__ xin = (hop == 0) ? g_x0T : (g_xh + (hop - 1) * NEB);
    float* xout = g_xh + hop * NEB;
    const unsigned* __restrict__ lmin = g_lm + hop * NE;
    unsigned* lmout = g_lm + (hop + 1) * NE;

    int lane = tid & 31;
    int t8 = lane >> 2;            // 0..7: triple slot this iteration
    int q2 = lane & 3;             // handles quads 2*q2 and 2*q2+1
    int t = sblk * 256 + tid;

    int s_i = 0, r_i = 0, o_i = 0;
    unsigned lm_i = 0;
    if (t < NT) {
        s_i = subj[t];
        lm_i = lmin[s_i];
        if (lm_i) { r_i = rel[t]; o_i = obj[t]; }
    }
    unsigned bal = __ballot_sync(0xffffffffu, lm_i != 0);
    while (bal) {
        int myi = __fns(bal, 0, t8 + 1);       // (t8+1)-th set bit, or -1
        int i7  = __fns(bal, 0, 8);            // 8th set bit (for clearing)
        bool on = (myi >= 0);
        int src = on ? myi : 0;
        int s = __shfl_sync(0xffffffffu, s_i, src);
        int r = __shfl_sync(0xffffffffu, r_i, src);
        int o = __shfl_sync(0xffffffffu, o_i, src);
        unsigned lmw = __shfl_sync(0xffffffffu, lm_i, src);
        unsigned m8 = 0;
        if (on) {
#pragma unroll
            for (int h = 0; h < 2; h++) {
                int quad = q2 * 2 + h;
                unsigned nib = (lmw >> (quad * 4)) & 0xFu;
                if (nib) {
                    float4 xv = *reinterpret_cast<const float4*>(
                        &xin[(size_t)s * NB + quad * 4]);
                    float4 rv = *reinterpret_cast<const float4*>(
                        &rT[r * NB + quad * 4]);
                    float4 p;
                    p.x = xv.x * rv.x; p.y = xv.y * rv.y;
                    p.z = xv.z * rv.z; p.w = xv.w * rv.w;
                    unsigned m4 = (p.x != 0.f) | ((p.y != 0.f) << 1) |
                                  ((p.z != 0.f) << 2) | ((p.w != 0.f) << 3);
                    if (m4) {
                        float* dst = &xout[(size_t)o * NB + quad * 4];
                        asm volatile("red.global.add.v4.f32 [%0], {%1,%2,%3,%4};"
                                     :: "l"(dst), "f"(p.x), "f"(p.y),
                                        "f"(p.z), "f"(p.w)
                                     : "memory");
                        m8 |= m4 << (quad * 4);
                    }
                }
            }
        }
        // or-reduce m8 across the 4 lanes of this triple (width=4)
        m8 |= __shfl_down_sync(0xffffffffu, m8, 2, 4);
        m8 |= __shfl_down_sync(0xffffffffu, m8, 1, 4);
        if (on && q2 == 0 && m8)
            atomicOr(&lmout[o], m8);
        // clear the (up to 8) consumed low set bits
        if (i7 < 0) bal = 0;
        else        bal &= ~((2u << i7) - 1);
    }
}

#define B_SC ((NT + 255) / 256)   // 3907 scatter blocks

// ============ phase 2: gemm_hop1 (NJ*2 blocks) + scatter hop0 ===============
__global__ void k_phase2(const int* __restrict__ subj, const int* __restrict__ rel,
                         const int* __restrict__ obj,
                         const float* __restrict__ W_inf,
                         const float* __restrict__ W_att) {
    int bid = blockIdx.x, tid = threadIdx.x;
    if (bid < NJ * 2)
        gemm_hop_body(W_inf, W_att, 1, bid >> 1, bid & 1, tid & 31, tid >> 5);
    else
        scatter_body(subj, rel, obj, 0, bid - NJ * 2, tid);
}

// ============ phase 3: gemm_hop2 (NJ*4 blocks) + scatter hop1 ===============
__global__ void k_phase3(const int* __restrict__ subj, const int* __restrict__ rel,
                         const int* __restrict__ obj,
                         const float* __restrict__ W_inf,
                         const float* __restrict__ W_att) {
    int bid = blockIdx.x, tid = threadIdx.x;
    if (bid < NJ * 4)
        gemm_hop_body(W_inf, W_att, 2, bid >> 2, bid & 3, tid & 31, tid >> 5);
    else
        scatter_body(subj, rel, obj, 1, bid - NJ * 4, tid);
}

// ============ phase 4: scatter hop2 =========================================
__global__ void k_phase4(const int* __restrict__ subj, const int* __restrict__ rel,
                         const int* __restrict__ obj) {
    scatter_body(subj, rel, obj, 2, blockIdx.x, threadIdx.x);
}

// ============ phase 5: softmax + masked combine + transpose out =============
__global__ void k_combine(float* __restrict__ out) {
    __shared__ float s[32][33];
    int lane = threadIdx.x & 31, ty = threadIdx.x >> 5;
    float c0 = g_c[lane], c1 = g_c[NB + lane], c2 = g_c[2 * NB + lane];
    float m = fmaxf(c0, fmaxf(c1, c2));
    float e0 = expf(c0 - m), e1 = expf(c1 - m), e2 = expf(c2 - m);
    float inv = 1.0f / (e0 + e1 + e2);
    float a0 = e0 * inv, a1 = e1 * inv, a2 = e2 * inv;

    int ebase = blockIdx.x * 32;
#pragma unroll
    for (int row = ty; row < 32; row += 8) {           // row = e offset, lane = b
        int e = ebase + row;
        int idx = e * NB + lane;
        float v = 0.f;
        if (g_lm[NE + e])     v += a0 * g_xh[idx];
        if (g_lm[2 * NE + e]) v += a1 * g_xh[NEB + idx];
        if (g_lm[3 * NE + e]) v += a2 * g_xh[2 * NEB + idx];
        s[row][lane] = v;
    }
    __syncthreads();
#pragma unroll
    for (int row = ty; row < 32; row += 8)             // row = b, lane = e offset
        out[(size_t)row * NE + ebase + lane] = s[lane][row];
}

extern "C" void kernel_launch(void* const* d_in, const int* in_sizes, int n_in,
                              void* d_out, int out_size) {
    const float* x     = (const float*)d_in[0];
    const float* h_q   = (const float*)d_in[1];
    const float* W_inf = (const float*)d_in[2];
    const float* W_att = (const float*)d_in[3];
    const int*   subj  = (const int*)d_in[4];
    const int*   rel   = (const int*)d_in[5];
    const int*   obj   = (const int*)d_in[6];
    float* out = (float*)d_out;

    k_zero_acc<<<(3 * NR * NB + 255) / 256, 256>>>();
    k_phase1<<<B_P1, 256>>>(x, h_q, W_inf, W_att);
    k_phase2<<<NJ * 2 + B_SC, 256>>>(subj, rel, obj, W_inf, W_att);
    k_phase3<<<NJ * 4 + B_SC, 256>>>(subj, rel, obj, W_inf, W_att);
    k_phase4<<<B_SC, 256>>>(subj, rel, obj);
    k_combine<<<NE / 32, 256>>>(out);
}